// round 17
// baseline (speedup 1.0000x reference)
#include <cuda_runtime.h>
#include <stdint.h>

#define BATCH 32
#define NPTS  16384
#define NROT  24
#define IMS   64
#define NPIX  4096
#define NIMG  768
#define TOT   (NIMG * NPIX)            // 3,145,728
#define NBUCK 65                       // 64 py rows + 1 py-OOR bucket
#define CAP   1024                     // max real bucket ~530

// Winner keys (p+1). max key <=> max n within a batch <=> last-write-wins.
// All scratch zero-init at load; scatter epilogue + cleanup re-zero each call.
__device__ __align__(16) unsigned g_win[TOT];      // 12.6 MB, L2-resident
__device__ unsigned g_spill[NIMG];                 // OOR winners, 1 per image
__device__ unsigned g_cnt[BATCH * NBUCK];
__device__ unsigned g_buck[BATCH * NBUCK * CAP];   // point ids

// ---------------------------------------------------------------- kernel 1
// Bucket points by (batch, py). py is rotation-invariant (rotation about y).
__global__ __launch_bounds__(256) void bucket_kernel(const float* __restrict__ xyz)
{
    __shared__ unsigned scnt[NBUCK], sbase[NBUCK];
    int tid = threadIdx.x;
    if (tid < NBUCK) scnt[tid] = 0u;
    __syncthreads();

    int p = blockIdx.x * 256 + tid;     // block lies within one batch
    int b = p >> 14;
    float y = xyz[p * 3 + 1];
    int py = __float2int_rn(fmaf(y, 16.0f, 32.0f));  // == rn((y+2)/0.0625), exact
    int bk = ((unsigned)py < IMS) ? py : 64;         // OOR py -> bucket 64
    unsigned rank = atomicAdd(&scnt[bk], 1u);
    __syncthreads();

    if (tid < NBUCK && scnt[tid])
        sbase[tid] = atomicAdd(&g_cnt[b * NBUCK + tid], scnt[tid]);
    __syncthreads();

    g_buck[(b * NBUCK + bk) * CAP + sbase[bk] + rank] = (unsigned)p;
}

// ---------------------------------------------------------------- kernel 2
// One CTA per (batch, bucket), LPT-ordered (center rows first). Bucket (b,bk)
// exclusively owns output rows (b, r, py=bk): OOR writes go to g_spill, so
// after fencing its own atomics the CTA can unpack its rows in-place.
__global__ __launch_bounds__(256) void scatter_kernel(const float* __restrict__ xyz,
                                                      const float* __restrict__ rot,
                                                      float* __restrict__ out)
{
    __shared__ float4 srot[NROT];   // (m00, m02, m20, m22)
    __shared__ unsigned s_red[8];
    int tid = threadIdx.x;
    if (tid < NROT) {
        const float* m = rot + tid * 9;
        srot[tid] = make_float4(m[0], m[2], m[6], m[8]);
    }
    __syncthreads();

    int bid = blockIdx.x;
    int b, bk;
    if (bid < BATCH * IMS) {
        b = bid & 31;                               // 32 same-size CTAs adjacent
        int i = bid >> 5;                           // centrality rank 0..63
        bk = (i & 1) ? (32 - ((i + 1) >> 1)) : (32 + (i >> 1));
    } else {
        b = bid - BATCH * IMS;                      // py-OOR buckets last
        bk = 64;
    }

    unsigned cnt = g_cnt[b * NBUCK + bk];
    const unsigned* __restrict__ buck = g_buck + (size_t)(b * NBUCK + bk) * CAP;
    unsigned* __restrict__ spillb = g_spill + b * NROT;

    if (bk == 64) {
        // py-OOR: masked in every rotation -> pixel (0,0) of all 24 images.
        unsigned best = 0u;
        for (unsigned i = tid; i < cnt; i += 256) best = max(best, buck[i] + 1u);
        best = __reduce_max_sync(0xffffffffu, best);
        if ((tid & 31) == 0) s_red[tid >> 5] = best;
        __syncthreads();
        if (tid < NROT) {
            unsigned m = s_red[0];
#pragma unroll
            for (int j = 1; j < 8; j++) m = max(m, s_red[j]);
            if (m) atomicMax(spillb + tid, m);
        }
        return;
    }

    size_t rowbase = (size_t)b * NROT * NPIX + bk * IMS;   // g_win/out row start
    for (unsigned i = tid; i < cnt; i += 256) {
        unsigned p = buck[i];
        unsigned key = p + 1u;
        float x = xyz[p * 3 + 0];
        float z = xyz[p * 3 + 2];
#pragma unroll
        for (int r = 0; r < NROT; r++) {
            float4 m = srot[r];
            float xr = fmaf(m.y, z, m.x * x);            // matches XLA fma; 0*y exact
            int px = __float2int_rn(fmaf(xr, 16.0f, 32.0f)); // == rn((xr+2)*16)
            unsigned* addr = ((unsigned)px < IMS)
                           ? (g_win + rowbase + r * NPIX + px)
                           : (spillb + r);               // px-OOR -> spill slot
            atomicMax(addr, key);
        }
    }

    // ---- fused unpack: drain own REDGs, then this CTA's rows are final ----
    __threadfence();
    __syncthreads();
    for (int e = tid; e < NROT * IMS; e += 256) {
        int r = e >> 6, px = e & 63;
        if (bk == 0 && px == 0) continue;   // pixel (0,0): cleanup merges spill
        size_t gi = rowbase + (size_t)r * NPIX + px;
        unsigned w = __ldcg(g_win + gi);
        g_win[gi] = 0u;
        float val = 0.0f;
        if (w) {
            unsigned p = w - 1u;
            float x = xyz[p * 3 + 0];
            float z = xyz[p * 3 + 2];
            float zr = fmaf(srot[r].w, z, srot[r].z * x);
            // Exact RN /10: zr/10 is never a float rounding midpoint, so the
            // double product rounds to the correctly-rounded float quotient.
            val = (float)((double)zr * 0.1);
        }
        out[gi] = val;
    }
}

// ---------------------------------------------------------------- kernel 3
// Merge spill winners into pixel (0,0) of each image; reset residual scratch.
__global__ __launch_bounds__(256) void cleanup_kernel(const float* __restrict__ xyz,
                                                      const float* __restrict__ rot,
                                                      float* __restrict__ out)
{
    int t = blockIdx.x * 256 + threadIdx.x;
    if (t < BATCH * NBUCK) g_cnt[t] = 0u;
    if (t >= NIMG) return;

    int r = t % NROT;
    size_t gi = (size_t)t * NPIX;             // pixel (0,0) of image t
    unsigned w = max(__ldcg(g_win + gi), g_spill[t]);
    g_win[gi] = 0u;
    g_spill[t] = 0u;

    float val = 0.0f;
    if (w) {
        unsigned p = w - 1u;
        float x = xyz[p * 3 + 0];
        float z = xyz[p * 3 + 2];
        float zr = fmaf(rot[r * 9 + 8], z, rot[r * 9 + 6] * x);
        val = (float)((double)zr * 0.1);
    }
    out[gi] = val;
}

extern "C" void kernel_launch(void* const* d_in, const int* in_sizes, int n_in,
                              void* d_out, int out_size)
{
    const float* xyz = (const float*)d_in[0];   // [32, 16384, 3] f32
    const float* rot = (const float*)d_in[1];   // [24, 3, 3] f32
    float* out = (float*)d_out;                 // [32, 24, 64, 64] f32

    bucket_kernel<<<(BATCH * NPTS) / 256, 256>>>(xyz);
    scatter_kernel<<<BATCH * IMS + BATCH, 256>>>(xyz, rot, out);
    cleanup_kernel<<<(BATCH * NBUCK + 255) / 256, 256>>>(xyz, rot, out);
}